// round 8
// baseline (speedup 1.0000x reference)
#include <cuda_runtime.h>
#include <cstdint>

// Problem constants (n=1, C=256, t=8, h=64, w=64, heads=8)
#define HEADS 8
#define TT 8
#define HH 64
#define WW 64
#define SDIM (TT + HH + WW - 2)   // 134
#define SP (TT * HH * WW)          // 32768
#define PLANE (HH * WW)            // 4096
#define CDIM 256
#define CG (CDIM / HEADS)          // 32 channels per head

__device__ float g_pv[CDIM * SP];

using ull = unsigned long long;

__device__ __forceinline__ ull packf2(float lo, float hi) {
    ull r;
    asm("mov.b64 %0, {%1, %2};" : "=l"(r) : "f"(lo), "f"(hi));
    return r;
}
__device__ __forceinline__ void unpackf2(ull v, float& lo, float& hi) {
    asm("mov.b64 {%0, %1}, %2;" : "=f"(lo), "=f"(hi) : "l"(v));
}
__device__ __forceinline__ void ffma2(ull& d, ull a, ull b) {
    asm("fma.rn.f32x2 %0, %1, %2, %3;" : "=l"(d) : "l"(a), "l"(b), "l"(d));
}
__device__ __forceinline__ ull negf2(ull v) {
    return v ^ 0x8000000080000000ULL;
}

// ---------------------------------------------------------------------------
// Kernel 1: pv[o, s] = bias[o] + sum_c W[o, c] * V[c, s]
// R3 structure; Vs consumed via direct ull reinterpret (no pack MOVs).
// ---------------------------------------------------------------------------
__global__ void __launch_bounds__(256) conv_gemm_kernel(
    const float* __restrict__ V, const float* __restrict__ Wm,
    const float* __restrict__ bias)
{
    __shared__ float2 Ws2[16][32];
    __shared__ float Vs[16][256];

    const int tid = threadIdx.x;
    const int tx = tid & 31;
    const int ty = tid >> 5;
    const int oBase = blockIdx.y * 32;
    const int sBase = blockIdx.x * 256;

    ull acc[4][4];
    #pragma unroll
    for (int i = 0; i < 4; ++i) {
        float bv = bias[oBase + ty * 4 + i];
        ull pb = packf2(bv, bv);
        #pragma unroll
        for (int j = 0; j < 4; ++j) acc[i][j] = pb;
    }

    float4 wv;
    float4 vv[4];
    const int oo = tid >> 2;
    const int kb = (tid & 3) * 4;

    if (tid < 128) wv = *(const float4*)&Wm[(oBase + oo) * CDIM + 0 + kb];
    #pragma unroll
    for (int j = 0; j < 4; ++j) {
        int idx = tid + j * 256;
        int r = idx >> 6, c4 = idx & 63;
        vv[j] = *(const float4*)&V[(0 + r) * SP + sBase + c4 * 4];
    }

    for (int kk = 0; kk < CDIM; kk += 16) {
        __syncthreads();
        if (tid < 128) {
            Ws2[kb + 0][oo] = make_float2(wv.x, wv.x);
            Ws2[kb + 1][oo] = make_float2(wv.y, wv.y);
            Ws2[kb + 2][oo] = make_float2(wv.z, wv.z);
            Ws2[kb + 3][oo] = make_float2(wv.w, wv.w);
        }
        #pragma unroll
        for (int j = 0; j < 4; ++j) {
            int idx = tid + j * 256;
            int r = idx >> 6, c4 = idx & 63;
            *(float4*)&Vs[r][c4 * 4] = vv[j];
        }
        __syncthreads();

        int kn = kk + 16;
        if (kn < CDIM) {
            if (tid < 128) wv = *(const float4*)&Wm[(oBase + oo) * CDIM + kn + kb];
            #pragma unroll
            for (int j = 0; j < 4; ++j) {
                int idx = tid + j * 256;
                int r = idx >> 6, c4 = idx & 63;
                vv[j] = *(const float4*)&V[(kn + r) * SP + sBase + c4 * 4];
            }
        }

        #pragma unroll
        for (int k = 0; k < 16; ++k) {
            const ull* v0 = reinterpret_cast<const ull*>(&Vs[k][tx * 4]);
            const ull* v1 = reinterpret_cast<const ull*>(&Vs[k][128 + tx * 4]);
            ull bb0 = v0[0], bb1 = v0[1];
            ull bb2 = v1[0], bb3 = v1[1];
            #pragma unroll
            for (int i = 0; i < 4; ++i) {
                ull a2 = *reinterpret_cast<const ull*>(&Ws2[k][ty * 4 + i]);
                ffma2(acc[i][0], a2, bb0);
                ffma2(acc[i][1], a2, bb1);
                ffma2(acc[i][2], a2, bb2);
                ffma2(acc[i][3], a2, bb3);
            }
        }
    }

    #pragma unroll
    for (int i = 0; i < 4; ++i) {
        float r0, r1, r2, r3, r4, r5, r6, r7;
        unpackf2(acc[i][0], r0, r1);
        unpackf2(acc[i][1], r2, r3);
        unpackf2(acc[i][2], r4, r5);
        unpackf2(acc[i][3], r6, r7);
        float* dst = &g_pv[(oBase + ty * 4 + i) * SP + sBase];
        float4 o0 = {r0, r1, r2, r3};
        float4 o1 = {r4, r5, r6, r7};
        *(float4*)&dst[tx * 4] = o0;
        *(float4*)&dst[128 + tx * 4] = o1;
    }
}

// ---------------------------------------------------------------------------
// Kernel 2: t-sum (x-pair lanes, elementwise; zero pack MOVs in loop).
// 512 threads, pos chunk 128 (64 pairs). Thread: u=tid&63 (pos pair), cg=tid>>6
// (channels 4cg..4cg+3). Writes out (overwrite).
// ---------------------------------------------------------------------------
__global__ void __launch_bounds__(512) attn_t_kernel(
    const float* __restrict__ A, float* __restrict__ out)
{
    __shared__ float ats[8 * 8 * 128];   // [s][tau][pos]

    const int tid = threadIdx.x;
    const int u = tid & 63;              // pos pair
    const int cg = tid >> 6;             // 0..7
    const int pos0 = blockIdx.x * 128;
    const int b = blockIdx.y;
    const int cbase = b * CG;
    const int attb = b * SDIM * SP;

    for (int i = tid; i < 8192; i += 512) {
        int p_i = i & 127, tau_i = (i >> 7) & 7, s_i = i >> 10;
        ats[i] = A[attb + s_i * SP + tau_i * PLANE + pos0 + p_i];
    }

    // pv pairs in registers: [8s][4c]
    ull pvr[8][4];
    #pragma unroll
    for (int s = 0; s < 8; ++s)
        #pragma unroll
        for (int cc = 0; cc < 4; ++cc)
            pvr[s][cc] = *reinterpret_cast<const ull*>(
                &g_pv[(cbase + 4 * cg + cc) * SP + s * PLANE + pos0 + 2 * u]);
    __syncthreads();

    const ull z = 0;
    #pragma unroll 1
    for (int tau = 0; tau < 8; ++tau) {
        ull acc[4] = {z, z, z, z};
        #pragma unroll
        for (int s = 0; s < 8; ++s) {
            ull a2 = *reinterpret_cast<const ull*>(&ats[(s * 8 + tau) * 128 + 2 * u]);
            #pragma unroll
            for (int cc = 0; cc < 4; ++cc)
                ffma2(acc[cc], a2, pvr[s][cc]);
        }
        #pragma unroll
        for (int cc = 0; cc < 4; ++cc)
            *reinterpret_cast<ull*>(
                &out[(cbase + 4 * cg + cc) * SP + tau * PLANE + pos0 + 2 * u]) = acc[cc];
    }
}

// ---------------------------------------------------------------------------
// Kernel 3: h-sum, RMW. x-pair lanes (elementwise in x — no duplication).
// Block: (x-tile 16, tau, head) grid (4,8,8). 512 threads.
// Thread: xq=tid&3 (x=4xq..+3, 2 pairs), qg=(tid>>2)&15 (4 q), cg=tid>>6 (4 c).
// smem: pvh[64p][32c][16x] floats = 128KB. Pointer-walk A (R3-proven).
// ---------------------------------------------------------------------------
__global__ void __launch_bounds__(512) attn_h_kernel(
    const float* __restrict__ A, float* __restrict__ out)
{
    extern __shared__ float pvh[];   // [p][c][x]

    const int tid = threadIdx.x;
    const int xq = tid & 3;
    const int qg = (tid >> 2) & 15;
    const int cg = tid >> 6;            // 0..7
    const int x0 = blockIdx.x * 16;
    const int tau = blockIdx.y;
    const int b = blockIdx.z;
    const int cbase = b * CG;
    const int attb = b * SDIM * SP;

    // pv load: [p][c][x]
    for (int i = tid; i < 32768; i += 512) {
        int x = i & 15, c = (i >> 4) & 31, p = i >> 9;
        pvh[(p * 32 + c) * 16 + x] =
            g_pv[(cbase + c) * SP + tau * PLANE + p * 64 + x0 + x];
    }
    __syncthreads();

    ull acc[4][4][2];   // [qi][cc][pair]
    #pragma unroll
    for (int qi = 0; qi < 4; ++qi)
        #pragma unroll
        for (int cc = 0; cc < 4; ++cc) { acc[qi][cc][0] = 0; acc[qi][cc][1] = 0; }

    const float* Ahb = A + attb + TT * SP + tau * PLANE;
    int qv[4];
    const float* pA[4];
    #pragma unroll
    for (int qi = 0; qi < 4; ++qi) {
        qv[qi] = 4 * qg + qi;
        pA[qi] = Ahb + qv[qi] * 64 + x0 + 4 * xq;   // j=0 row
    }

    #pragma unroll 2
    for (int p = 0; p < 64; ++p) {
        ulonglong2 av[4];
        #pragma unroll
        for (int qi = 0; qi < 4; ++qi)
            av[qi] = __ldg((const ulonglong2*)pA[qi]);
        #pragma unroll
        for (int qi = 0; qi < 4; ++qi)
            pA[qi] += (p != qv[qi]) ? SP : 0;

        ull pw[4][2];
        #pragma unroll
        for (int cc = 0; cc < 4; ++cc) {
            const ull* s = reinterpret_cast<const ull*>(
                &pvh[(p * 32 + 4 * cg + cc) * 16 + 4 * xq]);
            pw[cc][0] = s[0];
            pw[cc][1] = s[1];
        }
        #pragma unroll
        for (int qi = 0; qi < 4; ++qi)
            #pragma unroll
            for (int cc = 0; cc < 4; ++cc) {
                ffma2(acc[qi][cc][0], av[qi].x, pw[cc][0]);
                ffma2(acc[qi][cc][1], av[qi].y, pw[cc][1]);
            }
    }

    // subtract the bogus p==q term
    #pragma unroll
    for (int qi = 0; qi < 4; ++qi) {
        int q = qv[qi];
        ulonglong2 bv = __ldg((const ulonglong2*)&Ahb[q * SP + q * 64 + x0 + 4 * xq]);
        ull nb0 = negf2(bv.x), nb1 = negf2(bv.y);
        #pragma unroll
        for (int cc = 0; cc < 4; ++cc) {
            const ull* s = reinterpret_cast<const ull*>(
                &pvh[(q * 32 + 4 * cg + cc) * 16 + 4 * xq]);
            ffma2(acc[qi][cc][0], nb0, s[0]);
            ffma2(acc[qi][cc][1], nb1, s[1]);
        }
    }

    // RMW store: per (qi, cc) one float4 (4 consecutive x)
    #pragma unroll
    for (int qi = 0; qi < 4; ++qi) {
        int q = qv[qi];
        #pragma unroll
        for (int cc = 0; cc < 4; ++cc) {
            float l0, h0, l1, h1;
            unpackf2(acc[qi][cc][0], l0, h0);
            unpackf2(acc[qi][cc][1], l1, h1);
            float* o = &out[(cbase + 4 * cg + cc) * SP + tau * PLANE + q * 64 + x0 + 4 * xq];
            float4 t = *(float4*)o;
            t.x += l0; t.y += h0; t.z += l1; t.w += h1;
            *(float4*)o = t;
        }
    }
}

// ---------------------------------------------------------------------------
// Kernel 4: w-sum, RMW. x-pair lanes; pv pre-duplicated in smem.
// Block: (q-tile 8, tau, head) grid (8,8,8). 512 threads.
// Thread: xo=tid&7 (x=8xo..+7, 4 pairs), cg=(tid>>3)&7 (4 c), qloc=tid>>6 (8 q).
// smem: pvd[8q][64p][33cpad] float2 = 135168 B (dup). j-space + epilogue fixes.
// ---------------------------------------------------------------------------
#define WPAD 33

__global__ void __launch_bounds__(512) attn_w_kernel(
    const float* __restrict__ A, float* __restrict__ out)
{
    extern __shared__ float2 pvd[];   // [q][p][WPAD]

    const int tid = threadIdx.x;
    const int xo = tid & 7;
    const int cg = (tid >> 3) & 7;
    const int qloc = tid >> 6;          // 0..7
    const int q0 = blockIdx.x * 8;
    const int tau = blockIdx.y;
    const int b = blockIdx.z;
    const int cbase = b * CG;
    const int attb = b * SDIM * SP;
    const int q = q0 + qloc;

    // load pv duplicated: [q][p][c]
    for (int i = tid; i < 16384; i += 512) {
        int p = i & 63, c = (i >> 6) & 31, qi = i >> 11;
        float v = g_pv[(cbase + c) * SP + tau * PLANE + (q0 + qi) * 64 + p];
        pvd[(qi * 64 + p) * WPAD + c] = make_float2(v, v);
    }
    __syncthreads();

    ull acc[4][4];   // [u (x pair: x=8xo+2u)][cc]
    #pragma unroll
    for (int u = 0; u < 4; ++u)
        #pragma unroll
        for (int cc = 0; cc < 4; ++cc) acc[u][cc] = 0;

    const float* Awq = A + attb + (TT + HH - 1) * SP + tau * PLANE + q * 64;
    const int thr = 8 * xo + 7;
    const float2* pvq = &pvd[(qloc * 64) * WPAD + 4 * cg];

    #pragma unroll 4
    for (int j = 0; j < 63; ++j) {
        ulonglong2 av0 = __ldg((const ulonglong2*)(Awq + j * SP + 8 * xo));
        ulonglong2 av1 = __ldg((const ulonglong2*)(Awq + j * SP + 8 * xo + 4));
        int p = j + (j >= thr ? 1 : 0);

        const float2* s = pvq + p * WPAD;
        ull d0 = *reinterpret_cast<const ull*>(s + 0);
        ull d1 = *reinterpret_cast<const ull*>(s + 1);
        ull d2 = *reinterpret_cast<const ull*>(s + 2);
        ull d3 = *reinterpret_cast<const ull*>(s + 3);

        ffma2(acc[0][0], av0.x, d0); ffma2(acc[0][1], av0.x, d1);
        ffma2(acc[0][2], av0.x, d2); ffma2(acc[0][3], av0.x, d3);
        ffma2(acc[1][0], av0.y, d0); ffma2(acc[1][1], av0.y, d1);
        ffma2(acc[1][2], av0.y, d2); ffma2(acc[1][3], av0.y, d3);
        ffma2(acc[2][0], av1.x, d0); ffma2(acc[2][1], av1.x, d1);
        ffma2(acc[2][2], av1.x, d2); ffma2(acc[2][3], av1.x, d3);
        ffma2(acc[3][0], av1.y, d0); ffma2(acc[3][1], av1.y, d1);
        ffma2(acc[3][2], av1.y, d2); ffma2(acc[3][3], av1.y, d3);
    }

    // corrections: for j = 8xo+jj (jj 0..6), lanes m <= jj used pv[j], need pv[j+1]
    #pragma unroll 1
    for (int jj = 0; jj < 7; ++jj) {
        int j = 8 * xo + jj;
        const float2* sj = pvq + j * WPAD;
        const float2* sj1 = pvq + (j + 1) * WPAD;
        ull dj[4], dj1[4];
        #pragma unroll
        for (int cc = 0; cc < 4; ++cc) {
            dj[cc]  = *reinterpret_cast<const ull*>(sj + cc);
            dj1[cc] = *reinterpret_cast<const ull*>(sj1 + cc);
        }
        // full pairs: u where 2u+1 <= jj; boundary pair when jj even: u=jj/2 (low lane only)
        for (int u = 0; 2 * u <= jj; ++u) {
            ull ap;
            if (2 * u + 1 <= jj) {
                ap = __ldg((const ull*)(Awq + j * SP + 8 * xo + 2 * u));
            } else {
                float a = __ldg(Awq + j * SP + 8 * xo + 2 * u);
                ap = packf2(a, 0.0f);
            }
            ull an = negf2(ap);
            #pragma unroll
            for (int cc = 0; cc < 4; ++cc) {
                ffma2(acc[u][cc], ap, dj1[cc]);
                ffma2(acc[u][cc], an, dj[cc]);
            }
        }
    }

    // RMW store: per cc, two float4 covering x = 8xo..8xo+7
    #pragma unroll
    for (int cc = 0; cc < 4; ++cc) {
        float v[8];
        #pragma unroll
        for (int u = 0; u < 4; ++u) unpackf2(acc[u][cc], v[2 * u], v[2 * u + 1]);
        float* o = &out[(cbase + 4 * cg + cc) * SP + tau * PLANE + q * 64 + 8 * xo];
        float4 t0 = *(float4*)o;
        float4 t1 = *(float4*)(o + 4);
        t0.x += v[0]; t0.y += v[1]; t0.z += v[2]; t0.w += v[3];
        t1.x += v[4]; t1.y += v[5]; t1.z += v[6]; t1.w += v[7];
        *(float4*)o = t0;
        *(float4*)(o + 4) = t1;
    }
}

// ---------------------------------------------------------------------------

extern "C" void kernel_launch(void* const* d_in, const int* in_sizes, int n_in,
                              void* d_out, int out_size) {
    (void)in_sizes; (void)n_in; (void)out_size;
    const float* A    = (const float*)d_in[0];
    const float* V    = (const float*)d_in[1];
    const float* Wm   = (const float*)d_in[2];
    const float* bias = (const float*)d_in[3];
    float* out = (float*)d_out;

    const int SMEM_H = 64 * 32 * 16 * (int)sizeof(float);    // 131072
    const int SMEM_W = 8 * 64 * WPAD * (int)sizeof(float2);  // 135168

    cudaFuncSetAttribute(attn_h_kernel, cudaFuncAttributeMaxDynamicSharedMemorySize, SMEM_H);
    cudaFuncSetAttribute(attn_w_kernel, cudaFuncAttributeMaxDynamicSharedMemorySize, SMEM_W);

    conv_gemm_kernel<<<dim3(SP / 256, CDIM / 32), 256>>>(V, Wm, bias);
    attn_t_kernel<<<dim3(PLANE / 128, HEADS), 512>>>(A, out);
    attn_h_kernel<<<dim3(4, TT, HEADS), 512, SMEM_H>>>(A, out);
    attn_w_kernel<<<dim3(8, TT, HEADS), 512, SMEM_W>>>(A, out);
}

// round 9
// speedup vs baseline: 1.0212x; 1.0212x over previous
#include <cuda_runtime.h>
#include <cstdint>

// Problem constants (n=1, C=256, t=8, h=64, w=64, heads=8)
#define HEADS 8
#define TT 8
#define HH 64
#define WW 64
#define SDIM (TT + HH + WW - 2)   // 134
#define SP (TT * HH * WW)          // 32768
#define PLANE (HH * WW)            // 4096
#define CDIM 256
#define CG (CDIM / HEADS)          // 32 channels per head

__device__ float g_pv[CDIM * SP];

using ull = unsigned long long;

__device__ __forceinline__ ull packf2(float lo, float hi) {
    ull r;
    asm("mov.b64 %0, {%1, %2};" : "=l"(r) : "f"(lo), "f"(hi));
    return r;
}
__device__ __forceinline__ void unpackf2(ull v, float& lo, float& hi) {
    asm("mov.b64 {%0, %1}, %2;" : "=f"(lo), "=f"(hi) : "l"(v));
}
__device__ __forceinline__ void ffma2(ull& d, ull a, ull b) {
    asm("fma.rn.f32x2 %0, %1, %2, %3;" : "=l"(d) : "l"(a), "l"(b), "l"(d));
}
__device__ __forceinline__ ull negf2(ull v) {
    return v ^ 0x8000000080000000ULL;
}

// ---------------------------------------------------------------------------
// Kernel 1: pv[o, s] = bias[o] + sum_c W[o, c] * V[c, s]
// R3 structure; Vs consumed via direct ull reinterpret (no pack MOVs).
// ---------------------------------------------------------------------------
__global__ void __launch_bounds__(256) conv_gemm_kernel(
    const float* __restrict__ V, const float* __restrict__ Wm,
    const float* __restrict__ bias)
{
    __shared__ float2 Ws2[16][32];
    __shared__ float Vs[16][256];

    const int tid = threadIdx.x;
    const int tx = tid & 31;
    const int ty = tid >> 5;
    const int oBase = blockIdx.y * 32;
    const int sBase = blockIdx.x * 256;

    ull acc[4][4];
    #pragma unroll
    for (int i = 0; i < 4; ++i) {
        float bv = bias[oBase + ty * 4 + i];
        ull pb = packf2(bv, bv);
        #pragma unroll
        for (int j = 0; j < 4; ++j) acc[i][j] = pb;
    }

    float4 wv;
    float4 vv[4];
    const int oo = tid >> 2;
    const int kb = (tid & 3) * 4;

    if (tid < 128) wv = *(const float4*)&Wm[(oBase + oo) * CDIM + 0 + kb];
    #pragma unroll
    for (int j = 0; j < 4; ++j) {
        int idx = tid + j * 256;
        int r = idx >> 6, c4 = idx & 63;
        vv[j] = *(const float4*)&V[(0 + r) * SP + sBase + c4 * 4];
    }

    for (int kk = 0; kk < CDIM; kk += 16) {
        __syncthreads();
        if (tid < 128) {
            Ws2[kb + 0][oo] = make_float2(wv.x, wv.x);
            Ws2[kb + 1][oo] = make_float2(wv.y, wv.y);
            Ws2[kb + 2][oo] = make_float2(wv.z, wv.z);
            Ws2[kb + 3][oo] = make_float2(wv.w, wv.w);
        }
        #pragma unroll
        for (int j = 0; j < 4; ++j) {
            int idx = tid + j * 256;
            int r = idx >> 6, c4 = idx & 63;
            *(float4*)&Vs[r][c4 * 4] = vv[j];
        }
        __syncthreads();

        int kn = kk + 16;
        if (kn < CDIM) {
            if (tid < 128) wv = *(const float4*)&Wm[(oBase + oo) * CDIM + kn + kb];
            #pragma unroll
            for (int j = 0; j < 4; ++j) {
                int idx = tid + j * 256;
                int r = idx >> 6, c4 = idx & 63;
                vv[j] = *(const float4*)&V[(kn + r) * SP + sBase + c4 * 4];
            }
        }

        #pragma unroll
        for (int k = 0; k < 16; ++k) {
            const ull* v0 = reinterpret_cast<const ull*>(&Vs[k][tx * 4]);
            const ull* v1 = reinterpret_cast<const ull*>(&Vs[k][128 + tx * 4]);
            ull bb0 = v0[0], bb1 = v0[1];
            ull bb2 = v1[0], bb3 = v1[1];
            #pragma unroll
            for (int i = 0; i < 4; ++i) {
                ull a2 = *reinterpret_cast<const ull*>(&Ws2[k][ty * 4 + i]);
                ffma2(acc[i][0], a2, bb0);
                ffma2(acc[i][1], a2, bb1);
                ffma2(acc[i][2], a2, bb2);
                ffma2(acc[i][3], a2, bb3);
            }
        }
    }

    #pragma unroll
    for (int i = 0; i < 4; ++i) {
        float r0, r1, r2, r3, r4, r5, r6, r7;
        unpackf2(acc[i][0], r0, r1);
        unpackf2(acc[i][1], r2, r3);
        unpackf2(acc[i][2], r4, r5);
        unpackf2(acc[i][3], r6, r7);
        float* dst = &g_pv[(oBase + ty * 4 + i) * SP + sBase];
        float4 o0 = {r0, r1, r2, r3};
        float4 o1 = {r4, r5, r6, r7};
        *(float4*)&dst[tx * 4] = o0;
        *(float4*)&dst[128 + tx * 4] = o1;
    }
}

// ---------------------------------------------------------------------------
// Kernel 2: t-sum (x-pair lanes, elementwise; zero pack MOVs in loop).
// 512 threads, pos chunk 128 (64 pairs). Thread: u=tid&63 (pos pair), cg=tid>>6
// (channels 4cg..4cg+3). Writes out (overwrite).
// ---------------------------------------------------------------------------
__global__ void __launch_bounds__(512) attn_t_kernel(
    const float* __restrict__ A, float* __restrict__ out)
{
    __shared__ float ats[8 * 8 * 128];   // [s][tau][pos]

    const int tid = threadIdx.x;
    const int u = tid & 63;              // pos pair
    const int cg = tid >> 6;             // 0..7
    const int pos0 = blockIdx.x * 128;
    const int b = blockIdx.y;
    const int cbase = b * CG;
    const int attb = b * SDIM * SP;

    for (int i = tid; i < 8192; i += 512) {
        int p_i = i & 127, tau_i = (i >> 7) & 7, s_i = i >> 10;
        ats[i] = A[attb + s_i * SP + tau_i * PLANE + pos0 + p_i];
    }

    // pv pairs in registers: [8s][4c]
    ull pvr[8][4];
    #pragma unroll
    for (int s = 0; s < 8; ++s)
        #pragma unroll
        for (int cc = 0; cc < 4; ++cc)
            pvr[s][cc] = *reinterpret_cast<const ull*>(
                &g_pv[(cbase + 4 * cg + cc) * SP + s * PLANE + pos0 + 2 * u]);
    __syncthreads();

    const ull z = 0;
    #pragma unroll 1
    for (int tau = 0; tau < 8; ++tau) {
        ull acc[4] = {z, z, z, z};
        #pragma unroll
        for (int s = 0; s < 8; ++s) {
            ull a2 = *reinterpret_cast<const ull*>(&ats[(s * 8 + tau) * 128 + 2 * u]);
            #pragma unroll
            for (int cc = 0; cc < 4; ++cc)
                ffma2(acc[cc], a2, pvr[s][cc]);
        }
        #pragma unroll
        for (int cc = 0; cc < 4; ++cc)
            *reinterpret_cast<ull*>(
                &out[(cbase + 4 * cg + cc) * SP + tau * PLANE + pos0 + 2 * u]) = acc[cc];
    }
}

// ---------------------------------------------------------------------------
// Kernel 3: h-sum, RMW. x-pair lanes (elementwise in x — no duplication).
// Block: (x-tile 16, tau, head) grid (4,8,8). 512 threads.
// Thread: xq=tid&3 (x=4xq..+3, 2 pairs), qg=(tid>>2)&15 (4 q), cg=tid>>6 (4 c).
// smem: pvh[64p][32c][16x] floats = 128KB. Pointer-walk A (R3-proven).
// ---------------------------------------------------------------------------
__global__ void __launch_bounds__(512) attn_h_kernel(
    const float* __restrict__ A, float* __restrict__ out)
{
    extern __shared__ float pvh[];   // [p][c][x]

    const int tid = threadIdx.x;
    const int xq = tid & 3;
    const int qg = (tid >> 2) & 15;
    const int cg = tid >> 6;            // 0..7
    const int x0 = blockIdx.x * 16;
    const int tau = blockIdx.y;
    const int b = blockIdx.z;
    const int cbase = b * CG;
    const int attb = b * SDIM * SP;

    // pv load: [p][c][x]
    for (int i = tid; i < 32768; i += 512) {
        int x = i & 15, c = (i >> 4) & 31, p = i >> 9;
        pvh[(p * 32 + c) * 16 + x] =
            g_pv[(cbase + c) * SP + tau * PLANE + p * 64 + x0 + x];
    }
    __syncthreads();

    ull acc[4][4][2];   // [qi][cc][pair]
    #pragma unroll
    for (int qi = 0; qi < 4; ++qi)
        #pragma unroll
        for (int cc = 0; cc < 4; ++cc) { acc[qi][cc][0] = 0; acc[qi][cc][1] = 0; }

    const float* Ahb = A + attb + TT * SP + tau * PLANE;
    int qv[4];
    const float* pA[4];
    #pragma unroll
    for (int qi = 0; qi < 4; ++qi) {
        qv[qi] = 4 * qg + qi;
        pA[qi] = Ahb + qv[qi] * 64 + x0 + 4 * xq;   // j=0 row
    }

    #pragma unroll 2
    for (int p = 0; p < 64; ++p) {
        ulonglong2 av[4];
        #pragma unroll
        for (int qi = 0; qi < 4; ++qi)
            av[qi] = __ldg((const ulonglong2*)pA[qi]);
        #pragma unroll
        for (int qi = 0; qi < 4; ++qi)
            pA[qi] += (p != qv[qi]) ? SP : 0;

        ull pw[4][2];
        #pragma unroll
        for (int cc = 0; cc < 4; ++cc) {
            const ull* s = reinterpret_cast<const ull*>(
                &pvh[(p * 32 + 4 * cg + cc) * 16 + 4 * xq]);
            pw[cc][0] = s[0];
            pw[cc][1] = s[1];
        }
        #pragma unroll
        for (int qi = 0; qi < 4; ++qi)
            #pragma unroll
            for (int cc = 0; cc < 4; ++cc) {
                ffma2(acc[qi][cc][0], av[qi].x, pw[cc][0]);
                ffma2(acc[qi][cc][1], av[qi].y, pw[cc][1]);
            }
    }

    // subtract the bogus p==q term
    #pragma unroll
    for (int qi = 0; qi < 4; ++qi) {
        int q = qv[qi];
        ulonglong2 bv = __ldg((const ulonglong2*)&Ahb[q * SP + q * 64 + x0 + 4 * xq]);
        ull nb0 = negf2(bv.x), nb1 = negf2(bv.y);
        #pragma unroll
        for (int cc = 0; cc < 4; ++cc) {
            const ull* s = reinterpret_cast<const ull*>(
                &pvh[(q * 32 + 4 * cg + cc) * 16 + 4 * xq]);
            ffma2(acc[qi][cc][0], nb0, s[0]);
            ffma2(acc[qi][cc][1], nb1, s[1]);
        }
    }

    // RMW store: per (qi, cc) one float4 (4 consecutive x)
    #pragma unroll
    for (int qi = 0; qi < 4; ++qi) {
        int q = qv[qi];
        #pragma unroll
        for (int cc = 0; cc < 4; ++cc) {
            float l0, h0, l1, h1;
            unpackf2(acc[qi][cc][0], l0, h0);
            unpackf2(acc[qi][cc][1], l1, h1);
            float* o = &out[(cbase + 4 * cg + cc) * SP + tau * PLANE + q * 64 + x0 + 4 * xq];
            float4 t = *(float4*)o;
            t.x += l0; t.y += h0; t.z += l1; t.w += h1;
            *(float4*)o = t;
        }
    }
}

// ---------------------------------------------------------------------------
// Kernel 4: w-sum, RMW. x-pair lanes; pv pre-duplicated in smem.
// Block: (q-tile 8, tau, head) grid (8,8,8). 512 threads.
// Thread: xo=tid&7 (x=8xo..+7, 4 pairs), cg=(tid>>3)&7 (4 c), qloc=tid>>6 (8 q).
// smem: pvd[8q][64p][33cpad] float2 = 135168 B (dup). j-space + epilogue fixes.
// ---------------------------------------------------------------------------
#define WPAD 33

__global__ void __launch_bounds__(512) attn_w_kernel(
    const float* __restrict__ A, float* __restrict__ out)
{
    extern __shared__ float2 pvd[];   // [q][p][WPAD]

    const int tid = threadIdx.x;
    const int xo = tid & 7;
    const int cg = (tid >> 3) & 7;
    const int qloc = tid >> 6;          // 0..7
    const int q0 = blockIdx.x * 8;
    const int tau = blockIdx.y;
    const int b = blockIdx.z;
    const int cbase = b * CG;
    const int attb = b * SDIM * SP;
    const int q = q0 + qloc;

    // load pv duplicated: [q][p][c]
    for (int i = tid; i < 16384; i += 512) {
        int p = i & 63, c = (i >> 6) & 31, qi = i >> 11;
        float v = g_pv[(cbase + c) * SP + tau * PLANE + (q0 + qi) * 64 + p];
        pvd[(qi * 64 + p) * WPAD + c] = make_float2(v, v);
    }
    __syncthreads();

    ull acc[4][4];   // [u (x pair: x=8xo+2u)][cc]
    #pragma unroll
    for (int u = 0; u < 4; ++u)
        #pragma unroll
        for (int cc = 0; cc < 4; ++cc) acc[u][cc] = 0;

    const float* Awq = A + attb + (TT + HH - 1) * SP + tau * PLANE + q * 64;
    const int thr = 8 * xo + 7;
    const float2* pvq = &pvd[(qloc * 64) * WPAD + 4 * cg];

    #pragma unroll 4
    for (int j = 0; j < 63; ++j) {
        ulonglong2 av0 = __ldg((const ulonglong2*)(Awq + j * SP + 8 * xo));
        ulonglong2 av1 = __ldg((const ulonglong2*)(Awq + j * SP + 8 * xo + 4));
        int p = j + (j >= thr ? 1 : 0);

        const float2* s = pvq + p * WPAD;
        ull d0 = *reinterpret_cast<const ull*>(s + 0);
        ull d1 = *reinterpret_cast<const ull*>(s + 1);
        ull d2 = *reinterpret_cast<const ull*>(s + 2);
        ull d3 = *reinterpret_cast<const ull*>(s + 3);

        ffma2(acc[0][0], av0.x, d0); ffma2(acc[0][1], av0.x, d1);
        ffma2(acc[0][2], av0.x, d2); ffma2(acc[0][3], av0.x, d3);
        ffma2(acc[1][0], av0.y, d0); ffma2(acc[1][1], av0.y, d1);
        ffma2(acc[1][2], av0.y, d2); ffma2(acc[1][3], av0.y, d3);
        ffma2(acc[2][0], av1.x, d0); ffma2(acc[2][1], av1.x, d1);
        ffma2(acc[2][2], av1.x, d2); ffma2(acc[2][3], av1.x, d3);
        ffma2(acc[3][0], av1.y, d0); ffma2(acc[3][1], av1.y, d1);
        ffma2(acc[3][2], av1.y, d2); ffma2(acc[3][3], av1.y, d3);
    }

    // corrections: for j = 8xo+jj (jj 0..6), lanes m <= jj used pv[j], need pv[j+1]
    #pragma unroll 1
    for (int jj = 0; jj < 7; ++jj) {
        int j = 8 * xo + jj;
        const float2* sj = pvq + j * WPAD;
        const float2* sj1 = pvq + (j + 1) * WPAD;
        ull dj[4], dj1[4];
        #pragma unroll
        for (int cc = 0; cc < 4; ++cc) {
            dj[cc]  = *reinterpret_cast<const ull*>(sj + cc);
            dj1[cc] = *reinterpret_cast<const ull*>(sj1 + cc);
        }
        // full pairs: u where 2u+1 <= jj; boundary pair when jj even: u=jj/2 (low lane only)
        for (int u = 0; 2 * u <= jj; ++u) {
            ull ap;
            if (2 * u + 1 <= jj) {
                ap = __ldg((const ull*)(Awq + j * SP + 8 * xo + 2 * u));
            } else {
                float a = __ldg(Awq + j * SP + 8 * xo + 2 * u);
                ap = packf2(a, 0.0f);
            }
            ull an = negf2(ap);
            #pragma unroll
            for (int cc = 0; cc < 4; ++cc) {
                ffma2(acc[u][cc], ap, dj1[cc]);
                ffma2(acc[u][cc], an, dj[cc]);
            }
        }
    }

    // RMW store: per cc, two float4 covering x = 8xo..8xo+7
    #pragma unroll
    for (int cc = 0; cc < 4; ++cc) {
        float v[8];
        #pragma unroll
        for (int u = 0; u < 4; ++u) unpackf2(acc[u][cc], v[2 * u], v[2 * u + 1]);
        float* o = &out[(cbase + 4 * cg + cc) * SP + tau * PLANE + q * 64 + 8 * xo];
        float4 t0 = *(float4*)o;
        float4 t1 = *(float4*)(o + 4);
        t0.x += v[0]; t0.y += v[1]; t0.z += v[2]; t0.w += v[3];
        t1.x += v[4]; t1.y += v[5]; t1.z += v[6]; t1.w += v[7];
        *(float4*)o = t0;
        *(float4*)(o + 4) = t1;
    }
}

// ---------------------------------------------------------------------------

extern "C" void kernel_launch(void* const* d_in, const int* in_sizes, int n_in,
                              void* d_out, int out_size) {
    (void)in_sizes; (void)n_in; (void)out_size;
    const float* A    = (const float*)d_in[0];
    const float* V    = (const float*)d_in[1];
    const float* Wm   = (const float*)d_in[2];
    const float* bias = (const float*)d_in[3];
    float* out = (float*)d_out;

    const int SMEM_H = 64 * 32 * 16 * (int)sizeof(float);    // 131072
    const int SMEM_W = 8 * 64 * WPAD * (int)sizeof(float2);  // 135168

    cudaFuncSetAttribute(attn_h_kernel, cudaFuncAttributeMaxDynamicSharedMemorySize, SMEM_H);
    cudaFuncSetAttribute(attn_w_kernel, cudaFuncAttributeMaxDynamicSharedMemorySize, SMEM_W);

    conv_gemm_kernel<<<dim3(SP / 256, CDIM / 32), 256>>>(V, Wm, bias);
    attn_t_kernel<<<dim3(PLANE / 128, HEADS), 512>>>(A, out);
    attn_h_kernel<<<dim3(4, TT, HEADS), 512, SMEM_H>>>(A, out);
    attn_w_kernel<<<dim3(8, TT, HEADS), 512, SMEM_W>>>(A, out);
}